// round 1
// baseline (speedup 1.0000x reference)
#include <cuda_runtime.h>
#include <cstddef>

// Problem constants (fixed by setup_inputs)
#define BB 4096
#define DD 4096
#define HH 2048
#define TT 8
#define MM 6

// Scratch (device globals: allocation-free per harness rules)
__device__ float g_h[(size_t)BB * HH];    // relu(x@W1+b1)   32 MB
__device__ float g_enc[(size_t)BB * HH];  // h@W2+b2         32 MB
__device__ float g_xs[(size_t)BB * DD];   // sorted rows of x 64 MB
__device__ int   g_idx[BB * TT];          // argmax routing

// ---------------------------------------------------------------------------
// SGEMM 128x128 tile, BK=8, 256 threads, 8x8 per-thread microtile, fp32 FMA.
// sel==0:  C=g_h   = relu(A_in @ B_in + bias)      (A_in = x)
// sel==1:  C=g_enc =      g_h  @ B_in + bias
// ---------------------------------------------------------------------------
__global__ __launch_bounds__(256, 2)
void sgemm_kernel(const float* __restrict__ A_in, const float* __restrict__ Bm,
                  const float* __restrict__ bias, int sel, int K)
{
    __shared__ float As[8][128];
    __shared__ float Bs[8][128];

    const int N = HH;
    const float* A = (sel == 0) ? A_in : g_h;
    float* C       = (sel == 0) ? g_h  : g_enc;

    int bx = blockIdx.x;          // N tile
    int by = blockIdx.y;          // M tile
    int t  = threadIdx.x;
    int tx = t & 15;              // 0..15
    int ty = t >> 4;              // 0..15

    const float* Ag = A + (size_t)(by * 128) * K;
    const float* Bg = Bm + (size_t)(bx * 128);

    float acc[8][8];
#pragma unroll
    for (int i = 0; i < 8; i++)
#pragma unroll
        for (int j = 0; j < 8; j++) acc[i][j] = 0.0f;

    int aRow = t >> 1;            // 0..127
    int aCol = (t & 1) * 4;       // 0 or 4
    int bRow = t >> 5;            // 0..7
    int bCol = (t & 31) * 4;      // 0..124

    for (int k0 = 0; k0 < K; k0 += 8) {
        float4 av = *(const float4*)(Ag + (size_t)aRow * K + k0 + aCol);
        As[aCol + 0][aRow] = av.x;
        As[aCol + 1][aRow] = av.y;
        As[aCol + 2][aRow] = av.z;
        As[aCol + 3][aRow] = av.w;
        float4 bv = *(const float4*)(Bg + (size_t)(k0 + bRow) * N + bCol);
        *(float4*)&Bs[bRow][bCol] = bv;
        __syncthreads();

#pragma unroll
        for (int kk = 0; kk < 8; kk++) {
            float ar[8], br[8];
#pragma unroll
            for (int i = 0; i < 8; i++) ar[i] = As[kk][ty * 8 + i];
#pragma unroll
            for (int j = 0; j < 8; j++) br[j] = Bs[kk][tx * 8 + j];
#pragma unroll
            for (int i = 0; i < 8; i++)
#pragma unroll
                for (int j = 0; j < 8; j++)
                    acc[i][j] = fmaf(ar[i], br[j], acc[i][j]);
        }
        __syncthreads();
    }

    // Epilogue: bias (+ relu for sel==0), vectorized store
#pragma unroll
    for (int i = 0; i < 8; i++) {
        int row = by * 128 + ty * 8 + i;
        float* crow = C + (size_t)row * N + bx * 128 + tx * 8;
#pragma unroll
        for (int j4 = 0; j4 < 2; j4++) {
            int col = bx * 128 + tx * 8 + j4 * 4;
            float4 v;
            v.x = acc[i][j4 * 4 + 0] + bias[col + 0];
            v.y = acc[i][j4 * 4 + 1] + bias[col + 1];
            v.z = acc[i][j4 * 4 + 2] + bias[col + 2];
            v.w = acc[i][j4 * 4 + 3] + bias[col + 3];
            if (sel == 0) {
                v.x = fmaxf(v.x, 0.f); v.y = fmaxf(v.y, 0.f);
                v.z = fmaxf(v.z, 0.f); v.w = fmaxf(v.w, 0.f);
            }
            *(float4*)(crow + j4 * 4) = v;
        }
    }
}

// ---------------------------------------------------------------------------
// logits = g_enc @ Ws + bs ; write logits to out tail (optional) ; argmax->g_idx
// 16 rows per CTA, 256 threads; K staged in smem chunks of 128.
// ---------------------------------------------------------------------------
__global__ __launch_bounds__(256, 4)
void logits_argmax_kernel(const float* __restrict__ Ws, const float* __restrict__ bs,
                          float* __restrict__ out_logits, int write_logits)
{
    __shared__ float es[16][128];
    __shared__ float ws[128][48];
    __shared__ float ls[16][48];

    int b0 = blockIdx.x * 16;
    int t  = threadIdx.x;
    int r  = t >> 4;   // 0..15 (row)
    int c  = t & 15;   // 0..15 (col group base)

    float acc0 = 0.f, acc1 = 0.f, acc2 = 0.f;

    for (int k0 = 0; k0 < HH; k0 += 128) {
        // enc chunk: 16 x 128 = 512 float4
        for (int i = t; i < 512; i += 256) {
            int rr = i >> 5, cc = (i & 31) << 2;
            *(float4*)&es[rr][cc] =
                *(const float4*)(g_enc + (size_t)(b0 + rr) * HH + k0 + cc);
        }
        // Ws chunk: 128 x 48 = 1536 float4
        for (int i = t; i < 1536; i += 256) {
            int rr = i / 12, cc = (i % 12) << 2;
            *(float4*)&ws[rr][cc] = *(const float4*)(Ws + (size_t)(k0 + rr) * 48 + cc);
        }
        __syncthreads();
#pragma unroll 4
        for (int k = 0; k < 128; k++) {
            float e = es[r][k];
            acc0 = fmaf(e, ws[k][c],      acc0);
            acc1 = fmaf(e, ws[k][c + 16], acc1);
            acc2 = fmaf(e, ws[k][c + 32], acc2);
        }
        __syncthreads();
    }

    ls[r][c]      = acc0 + bs[c];
    ls[r][c + 16] = acc1 + bs[c + 16];
    ls[r][c + 32] = acc2 + bs[c + 32];
    __syncthreads();

    if (write_logits) {
        for (int i = t; i < 16 * 48; i += 256) {
            int rr = i / 48, cc = i % 48;
            out_logits[(size_t)(b0 + rr) * 48 + cc] = ls[rr][cc];
        }
    }
    // argmax per (row, step): first-max tie-breaking like jnp.argmax
    if (t < 128) {
        int rr = t >> 3, tt = t & 7;
        const float* lp = &ls[rr][tt * 6];
        float best = lp[0]; int bi = 0;
#pragma unroll
        for (int m = 1; m < 6; m++) {
            float v = lp[m];
            if (v > best) { best = v; bi = m; }
        }
        g_idx[(b0 + rr) * TT + tt] = bi;
    }
}

// ---------------------------------------------------------------------------
// Bitonic sort of each row of x (4096 fp32) in shared memory -> g_xs
// ---------------------------------------------------------------------------
__global__ __launch_bounds__(1024, 2)
void sort_rows_kernel(const float* __restrict__ x)
{
    __shared__ float s[4096];
    int b = blockIdx.x;
    const float* xp = x + (size_t)b * DD;
    for (int i = threadIdx.x; i < 4096; i += 1024) s[i] = xp[i];
    __syncthreads();

    for (int k = 2; k <= 4096; k <<= 1) {
        for (int j = k >> 1; j > 0; j >>= 1) {
#pragma unroll
            for (int base = 0; base < 4096; base += 1024) {
                int i   = base + threadIdx.x;
                int ixj = i ^ j;
                if (ixj > i) {
                    bool asc = ((i & k) == 0);
                    float a = s[i], bb = s[ixj];
                    if ((a > bb) == asc) { s[i] = bb; s[ixj] = a; }
                }
            }
            __syncthreads();
        }
    }
    float* op = g_xs + (size_t)b * DD;
    for (int i = threadIdx.x; i < 4096; i += 1024) op[i] = s[i];
}

// ---------------------------------------------------------------------------
// Per-sample scalar scan over (mode, a, b), then emit outputs[b,t,:] = a*p(x)+b
// mode bit1: sorted source; bit0: reversed read.
// ---------------------------------------------------------------------------
__global__ __launch_bounds__(256, 4)
void emit_kernel(const float* __restrict__ x,
                 const float* __restrict__ add_s, const float* __restrict__ sub_s,
                 const float* __restrict__ mul_s, const float* __restrict__ div_s,
                 float* __restrict__ out)
{
    __shared__ float sa[8], sb[8];
    __shared__ int   sm[8];
    int b = blockIdx.x;

    if (threadIdx.x == 0) {
        float A = 1.0f, Bc = 0.0f;
        int mode = 0;
        float ad = *add_s, su = *sub_s, mu = *mul_s;
        float dv = *div_s + 1e-5f;
#pragma unroll
        for (int t = 0; t < 8; t++) {
            int m = g_idx[b * 8 + t];
            switch (m) {
                case 0: mode = 2;              break;  // sort
                case 1: mode ^= 1;             break;  // reverse
                case 2: Bc += ad;              break;  // add
                case 3: Bc -= su;              break;  // sub
                case 4: A *= mu; Bc *= mu;     break;  // mul
                case 5: A /= dv; Bc /= dv;     break;  // div
            }
            sa[t] = A; sb[t] = Bc; sm[t] = mode;
        }
    }
    __syncthreads();

    const float4* xr  = (const float4*)(x   + (size_t)b * DD);
    const float4* xsr = (const float4*)(g_xs + (size_t)b * DD);
    float* ob = out + (size_t)b * ((size_t)TT * DD);
    const int Q = DD / 4;  // 1024 float4 per row

#pragma unroll 1
    for (int t = 0; t < 8; t++) {
        float A = sa[t], Bc = sb[t];
        int mode = sm[t];
        const float4* src = (mode & 2) ? xsr : xr;
        bool rev = (mode & 1);
        float4* op = (float4*)(ob + (size_t)t * DD);
        for (int i = threadIdx.x; i < Q; i += 256) {
            float4 v;
            if (!rev) {
                v = src[i];
            } else {
                float4 u = src[Q - 1 - i];
                v.x = u.w; v.y = u.z; v.z = u.y; v.w = u.x;
            }
            v.x = fmaf(A, v.x, Bc);
            v.y = fmaf(A, v.y, Bc);
            v.z = fmaf(A, v.z, Bc);
            v.w = fmaf(A, v.w, Bc);
            op[i] = v;
        }
    }
}

// ---------------------------------------------------------------------------
extern "C" void kernel_launch(void* const* d_in, const int* in_sizes, int n_in,
                              void* d_out, int out_size)
{
    const float* x     = (const float*)d_in[0];
    const float* W1    = (const float*)d_in[1];
    const float* b1    = (const float*)d_in[2];
    const float* W2    = (const float*)d_in[3];
    const float* b2    = (const float*)d_in[4];
    const float* Ws    = (const float*)d_in[5];
    const float* bs    = (const float*)d_in[6];
    const float* add_s = (const float*)d_in[7];
    const float* sub_s = (const float*)d_in[8];
    const float* mul_s = (const float*)d_in[9];
    const float* div_s = (const float*)d_in[10];
    float* out = (float*)d_out;

    const size_t out_main   = (size_t)BB * TT * DD;           // outputs [B,T,D]
    const size_t out_need   = out_main + (size_t)BB * TT * MM; // + logits [B,T,M]
    int write_logits = ((size_t)out_size >= out_need) ? 1 : 0;
    float* out_logits = out + out_main;

    // Sort rows of x (independent of GEMM chain)
    sort_rows_kernel<<<BB, 1024>>>(x);

    // Controller GEMMs (fp32 FMA for argmax-exactness)
    dim3 g(HH / 128, BB / 128);   // (16, 32)
    sgemm_kernel<<<g, 256>>>(x, W1, b1, /*sel=*/0, /*K=*/DD);   // g_h = relu(x@W1+b1)
    sgemm_kernel<<<g, 256>>>(nullptr, W2, b2, /*sel=*/1, /*K=*/HH); // g_enc = g_h@W2+b2

    // logits + argmax routing
    logits_argmax_kernel<<<BB / 16, 256>>>(Ws, bs, out_logits, write_logits);

    // Collapsed scan + output emit
    emit_kernel<<<BB, 256>>>(x, add_s, sub_s, mul_s, div_s, out);
}